// round 14
// baseline (speedup 1.0000x reference)
#include <cuda_runtime.h>
#include <cuda_fp16.h>
#include <math.h>
#include <stdint.h>

#define B_ 32
#define S_ 2048
#define E_ 1024
#define D_ 1024
#define K_ 1024
#define M_ (S_ * B_)   // 65536

// GEMM tiling
#define CTAM 128
#define CTAN 128
#define CKS 64                 // K per chunk
#define NCHUNK (K_ / CKS)      // 16
#define NT (D_ / CTAN)         // 8
#define MT (M_ / CTAM)         // 512

// SMEM per stage: 2 tiles of 128 rows x 128B = 16KB each
#define OFF_AH 0
#define OFF_BH 16384
#define STAGE_BYTES 32768
#define NSTAGE 3
#define SMEM_BYTES (NSTAGE * STAGE_BYTES)   // 96KB dynamic

#define NSLOT 16   // score partials: 2 per N-block (wn halves) x NT blocks

__device__ float g_scores_p[NSLOT][B_ * S_];   // plain-store partials (no init)
__device__ float g_dec[B_ * D_];
__device__ __half g_ah[(size_t)M_ * K_];   // fp16(A)
__device__ __half g_bh[(size_t)D_ * K_];   // fp16(B)

// ---------------------------------------------------------------------------
__device__ __forceinline__ uint32_t smem_u32(const void* p) {
    uint32_t a;
    asm("{ .reg .u64 t; cvta.to.shared.u64 t, %1; cvt.u32.u64 %0, t; }" : "=r"(a) : "l"(p));
    return a;
}

// swizzled offset within a 128-row x 128B tile (8 16B-groups/row, 8-way XOR)
__device__ __forceinline__ uint32_t sw128(uint32_t row, uint32_t g) {
    return (row << 7) | (((g ^ row) & 7u) << 4);
}

__device__ __forceinline__ void ldsm4(uint32_t* r, uint32_t addr) {
    asm volatile("ldmatrix.sync.aligned.m8n8.x4.shared.b16 {%0,%1,%2,%3}, [%4];"
                 : "=r"(r[0]), "=r"(r[1]), "=r"(r[2]), "=r"(r[3]) : "r"(addr));
}

__device__ __forceinline__ void mma_f16(float* d, const uint32_t* a, const uint32_t* b) {
    asm volatile(
        "mma.sync.aligned.m16n8k16.row.col.f32.f16.f16.f32 "
        "{%0,%1,%2,%3}, {%4,%5,%6,%7}, {%8,%9}, {%0,%1,%2,%3};"
        : "+f"(d[0]), "+f"(d[1]), "+f"(d[2]), "+f"(d[3])
        : "r"(a[0]), "r"(a[1]), "r"(a[2]), "r"(a[3]), "r"(b[0]), "r"(b[1]));
}

#define CPA16(dst, src) \
    asm volatile("cp.async.cg.shared.global [%0], [%1], 16;" :: "r"(dst), "l"(src))

// tanh via rational approx (FMA-only, no MUFU in the hot path)
__device__ __forceinline__ float fast_tanh(float x) {
    float cx = fminf(fmaxf(x, -7.90531110763549805f), 7.90531110763549805f);
    float x2 = cx * cx;
    float p = fmaf(x2, -2.76076847742355e-16f, 2.00018790482477e-13f);
    p = fmaf(p, x2, -8.60467152213735e-11f);
    p = fmaf(p, x2, 5.12229709037114e-08f);
    p = fmaf(p, x2, 1.48572235717979e-05f);
    p = fmaf(p, x2, 6.37261928875436e-04f);
    p = fmaf(p, x2, 4.89352455891786e-03f);
    p = p * cx;
    float q = fmaf(x2, 1.19825839466702e-06f, 1.18534705686654e-04f);
    q = fmaf(q, x2, 2.26843463243900e-03f);
    q = fmaf(q, x2, 4.89352518554385e-03f);
    float r = __uint_as_float(0x7EF127EAu - __float_as_uint(q));
    r = r * (2.0f - q * r);
    r = r * (2.0f - q * r);
    r = r * (2.0f - q * r);
    return p * r;
}

// ---------------------------------------------------------------------------
// 0. init: zero only the context region of d_out (scores need no init now)
// ---------------------------------------------------------------------------
__global__ void init_kernel(float* __restrict__ out) {
    int i = blockIdx.x * blockDim.x + threadIdx.x;
    if (i < B_ * E_) out[i] = 0.f;
}

// ---------------------------------------------------------------------------
// 1. convert fp32 -> fp16 (16 elems/thread)
// ---------------------------------------------------------------------------
__global__ __launch_bounds__(256)
void cvt_h_kernel(const float* __restrict__ src, __half* __restrict__ dst) {
    size_t idx = ((size_t)blockIdx.x * 256 + threadIdx.x) * 16;
    const float4* s4 = (const float4*)(src + idx);
    float4 f0 = s4[0], f1 = s4[1], f2 = s4[2], f3 = s4[3];
    __half2 h[8];
    h[0] = __floats2half2_rn(f0.x, f0.y);
    h[1] = __floats2half2_rn(f0.z, f0.w);
    h[2] = __floats2half2_rn(f1.x, f1.y);
    h[3] = __floats2half2_rn(f1.z, f1.w);
    h[4] = __floats2half2_rn(f2.x, f2.y);
    h[5] = __floats2half2_rn(f2.z, f2.w);
    h[6] = __floats2half2_rn(f3.x, f3.y);
    h[7] = __floats2half2_rn(f3.z, f3.w);
    *(uint4*)(dst + idx) = *(uint4*)h;
    *(uint4*)(dst + idx + 8) = *(uint4*)(h + 4);
}

// ---------------------------------------------------------------------------
// 2. dec_proj: warp computes 4 outputs (d..d+3) for one b, hidden in regs
// ---------------------------------------------------------------------------
__global__ __launch_bounds__(256)
void dec_proj_kernel(const float* __restrict__ hidden, const float* __restrict__ Wd) {
    int warp = (blockIdx.x * blockDim.x + threadIdx.x) >> 5;
    int lane = threadIdx.x & 31;
    if (warp >= B_ * (D_ / 4)) return;
    int b = warp >> 8;               // / (D_/4)
    int dg = (warp & 255) << 2;
    const float4* h4 = (const float4*)(hidden + (size_t)b * D_);
    float4 ha[8];
#pragma unroll
    for (int i = 0; i < 8; i++) ha[i] = h4[lane + 32 * i];
    float s[4];
#pragma unroll
    for (int j = 0; j < 4; j++) {
        const float4* w4 = (const float4*)(Wd + (size_t)(dg + j) * D_);
        float acc = 0.f;
#pragma unroll
        for (int i = 0; i < 8; i++) {
            float4 w = w4[lane + 32 * i];
            acc += ha[i].x * w.x + ha[i].y * w.y + ha[i].z * w.z + ha[i].w * w.w;
        }
        s[j] = acc;
    }
#pragma unroll
    for (int j = 0; j < 4; j++)
#pragma unroll
        for (int o = 16; o; o >>= 1) s[j] += __shfl_down_sync(0xffffffffu, s[j], o);
    if (lane == 0)
        *(float4*)(g_dec + (size_t)b * D_ + dg) = make_float4(s[0], s[1], s[2], s[3]);
}

// ---------------------------------------------------------------------------
// 3. Fused scores GEMM: fp16, 3-stage cp.async ring, plain-store partials
// ---------------------------------------------------------------------------
__global__ __launch_bounds__(256, 2)
void score_mma_kernel(const float* __restrict__ v) {
    extern __shared__ __align__(1024) char smem[];
    const uint32_t sb = smem_u32(smem);

    const int tid = threadIdx.x;
    const int wid = tid >> 5;
    const int lane = tid & 31;
    const int wm = wid >> 1;          // 0..3
    const int wn = wid & 1;           // 0..1
    const int n_base = blockIdx.x * CTAN;
    const size_t m_base = (size_t)blockIdx.y * CTAM;

    // per-thread copy task: row lr (0..127), half lh -> 4 16B groups per tile
    const int lr = tid >> 1;
    const int lh = tid & 1;
    const __half* Ah_r = g_ah + (m_base + lr) * (size_t)K_;
    const __half* Bh_r = g_bh + (size_t)(n_base + lr) * K_;
    uint32_t so[4];
#pragma unroll
    for (int i = 0; i < 4; i++) so[i] = sw128(lr, lh * 4 + i);

#define PREFETCH(c, st)                                                       \
    {                                                                         \
        uint32_t stb_ = sb + (st) * STAGE_BYTES;                              \
        int ko_ = (c) * CKS;                                                  \
        _Pragma("unroll")                                                     \
        for (int i_ = 0; i_ < 4; i_++) {                                      \
            int ge_ = ko_ + (lh * 4 + i_) * 8;                                \
            CPA16(stb_ + OFF_AH + so[i_], Ah_r + ge_);                        \
            CPA16(stb_ + OFF_BH + so[i_], Bh_r + ge_);                        \
        }                                                                     \
    }

    float acc[2][8][4];
#pragma unroll
    for (int mt = 0; mt < 2; mt++)
#pragma unroll
        for (int j = 0; j < 8; j++)
#pragma unroll
            for (int cc = 0; cc < 4; cc++) acc[mt][j][cc] = 0.f;

    // ldmatrix per-lane address components
    const uint32_t a_row = wm * 32 + (lane & 15);
    const uint32_t a_kg = (uint32_t)(lane >> 4);
    const uint32_t b_row_lo = wn * 64 + (lane & 7) + ((lane & 16) ? 8 : 0);
    const uint32_t b_kg = (uint32_t)((lane >> 3) & 1);

    PREFETCH(0, 0);
    asm volatile("cp.async.commit_group;" ::: "memory");
    PREFETCH(1, 1);
    asm volatile("cp.async.commit_group;" ::: "memory");

    int st = 0, stp = 2;
    for (int c = 0; c < NCHUNK; c++) {
        asm volatile("cp.async.wait_group 1;" ::: "memory");
        __syncthreads();   // stage st ready; all warps done reading stage stp

        // early prefetch for chunk c+2 into the just-freed stage stp
        if (c + 2 < NCHUNK) PREFETCH(c + 2, stp);
        asm volatile("cp.async.commit_group;" ::: "memory");

        const uint32_t stb = sb + st * STAGE_BYTES;
#pragma unroll
        for (int ks = 0; ks < 4; ks++) {
            uint32_t ah[2][4];
#pragma unroll
            for (int mt = 0; mt < 2; mt++) {
                uint32_t off = sw128(a_row + mt * 16, 2 * ks + a_kg);
                ldsm4(ah[mt], stb + OFF_AH + off);
            }
#pragma unroll
            for (int half = 0; half < 2; half++) {
                uint32_t bh[4][2];
#pragma unroll
                for (int j2 = 0; j2 < 2; j2++) {
                    uint32_t off = sw128(b_row_lo + (half * 2 + j2) * 16, 2 * ks + b_kg);
                    uint32_t t[4];
                    ldsm4(t, stb + OFF_BH + off);
                    bh[j2 * 2][0] = t[0]; bh[j2 * 2][1] = t[1];
                    bh[j2 * 2 + 1][0] = t[2]; bh[j2 * 2 + 1][1] = t[3];
                }
#pragma unroll
                for (int mt = 0; mt < 2; mt++)
#pragma unroll
                    for (int j = 0; j < 4; j++)
                        mma_f16(acc[mt][half * 4 + j], ah[mt], bh[j]);
            }
        }
        st = (st == 2) ? 0 : st + 1;
        stp = (stp == 2) ? 0 : stp + 1;
    }
    asm volatile("cp.async.wait_group 0;" ::: "memory");
    __syncthreads();

    // ---- epilogue: stage dec tile + v into smem, tanh + v-dot, reduce ----
    float* sdec = (float*)smem;            // [32][128] = 16KB
    float* sv = (float*)(smem + 16384);    // [128]
    for (int i = tid; i < B_ * CTAN; i += 256) {
        int b = i >> 7, n = i & (CTAN - 1);
        sdec[b * CTAN + n] = g_dec[b * D_ + n_base + n];
    }
    if (tid < CTAN) sv[tid] = v[n_base + tid];
    __syncthreads();

    // plain-store partials: slot = 2*blockIdx.x + wn; full row coverage per slot
    float* slot = g_scores_p[2 * blockIdx.x + wn];
#pragma unroll
    for (int mt = 0; mt < 2; mt++) {
        int rowA = wm * 32 + mt * 16 + (lane >> 2);
        int b0 = rowA & 31, b1 = (rowA + 8) & 31;
        float s0 = 0.f, s1 = 0.f;
#pragma unroll
        for (int j = 0; j < 8; j++) {
            int nc = wn * 64 + j * 8 + (lane & 3) * 2;
            float v0 = sv[nc], v1 = sv[nc + 1];
            s0 = fmaf(fast_tanh(acc[mt][j][0] + sdec[b0 * CTAN + nc]), v0, s0);
            s0 = fmaf(fast_tanh(acc[mt][j][1] + sdec[b0 * CTAN + nc + 1]), v1, s0);
            s1 = fmaf(fast_tanh(acc[mt][j][2] + sdec[b1 * CTAN + nc]), v0, s1);
            s1 = fmaf(fast_tanh(acc[mt][j][3] + sdec[b1 * CTAN + nc + 1]), v1, s1);
        }
        s0 += __shfl_xor_sync(0xffffffffu, s0, 1);
        s0 += __shfl_xor_sync(0xffffffffu, s0, 2);
        s1 += __shfl_xor_sync(0xffffffffu, s1, 1);
        s1 += __shfl_xor_sync(0xffffffffu, s1, 2);
        if ((lane & 3) == 0) {
            size_t m0 = m_base + rowA;
            size_t m1 = m0 + 8;
            slot[(m0 & 31) * S_ + (m0 >> 5)] = s0;
            slot[(m1 & 31) * S_ + (m1 >> 5)] = s1;
        }
    }
}

// ---------------------------------------------------------------------------
// 4. softmax over S per batch (gathers NSLOT partials per element)
// ---------------------------------------------------------------------------
__global__ __launch_bounds__(256)
void softmax_kernel(float* __restrict__ wout) {
    int b = blockIdx.x;
    int tid = threadIdx.x;
    __shared__ float sm[256];

    float vals[8];
    float mx = -1e30f;
#pragma unroll
    for (int i = 0; i < 8; i++) {
        int idx = b * S_ + tid + i * 256;
        float s = 0.f;
#pragma unroll
        for (int k = 0; k < NSLOT; k++) s += g_scores_p[k][idx];
        vals[i] = s;
        mx = fmaxf(mx, s);
    }
    sm[tid] = mx; __syncthreads();
    for (int o = 128; o; o >>= 1) {
        if (tid < o) sm[tid] = fmaxf(sm[tid], sm[tid + o]);
        __syncthreads();
    }
    mx = sm[0]; __syncthreads();

    float sum = 0.f;
#pragma unroll
    for (int i = 0; i < 8; i++) { vals[i] = expf(vals[i] - mx); sum += vals[i]; }
    sm[tid] = sum; __syncthreads();
    for (int o = 128; o; o >>= 1) {
        if (tid < o) sm[tid] += sm[tid + o];
        __syncthreads();
    }
    float inv = 1.f / sm[0];
#pragma unroll
    for (int i = 0; i < 8; i++) wout[b * S_ + tid + i * 256] = vals[i] * inv;
}

// ---------------------------------------------------------------------------
// 5. context[b,e] = sum_s w[b,s] * enc_fp16[s,b,e]  (reads g_ah, half2)
// ---------------------------------------------------------------------------
#define CSPLIT 8
__global__ __launch_bounds__(256)
void context_kernel(const float* __restrict__ w, float* __restrict__ ctx) {
    int e2 = blockIdx.x * 256 + threadIdx.x;   // half2 index, 0..511
    int b = blockIdx.y;
    int s0 = blockIdx.z * (S_ / CSPLIT);
    const __half2* base = (const __half2*)g_ah + (size_t)b * (K_ / 2) + e2;
    const size_t str = (size_t)B_ * (K_ / 2);
    float ax0 = 0.f, ay0 = 0.f, ax1 = 0.f, ay1 = 0.f;
    float ax2 = 0.f, ay2 = 0.f, ax3 = 0.f, ay3 = 0.f;
#pragma unroll 2
    for (int s = s0; s < s0 + S_ / CSPLIT; s += 4) {
        float w0 = w[b * S_ + s + 0], w1 = w[b * S_ + s + 1];
        float w2 = w[b * S_ + s + 2], w3 = w[b * S_ + s + 3];
        float2 f0 = __half22float2(base[(size_t)(s + 0) * str]);
        float2 f1 = __half22float2(base[(size_t)(s + 1) * str]);
        float2 f2 = __half22float2(base[(size_t)(s + 2) * str]);
        float2 f3 = __half22float2(base[(size_t)(s + 3) * str]);
        ax0 = fmaf(w0, f0.x, ax0); ay0 = fmaf(w0, f0.y, ay0);
        ax1 = fmaf(w1, f1.x, ax1); ay1 = fmaf(w1, f1.y, ay1);
        ax2 = fmaf(w2, f2.x, ax2); ay2 = fmaf(w2, f2.y, ay2);
        ax3 = fmaf(w3, f3.x, ax3); ay3 = fmaf(w3, f3.y, ay3);
    }
    atomicAdd(&ctx[b * E_ + 2 * e2], (ax0 + ax1) + (ax2 + ax3));
    atomicAdd(&ctx[b * E_ + 2 * e2 + 1], (ay0 + ay1) + (ay2 + ay3));
}

// ---------------------------------------------------------------------------
extern "C" void kernel_launch(void* const* d_in, const int* in_sizes, int n_in,
                              void* d_out, int out_size) {
    const float* hidden = (const float*)d_in[0];  // [B,D]
    const float* enc    = (const float*)d_in[1];  // [S,B,E]
    const float* We     = (const float*)d_in[2];  // [D,E]
    const float* Wd     = (const float*)d_in[3];  // [D,D]
    const float* v      = (const float*)d_in[4];  // [D]
    float* out = (float*)d_out;                   // [B*E context | B*S weights]
    float* wout = out + B_ * E_;

    cudaFuncSetAttribute(score_mma_kernel,
                         cudaFuncAttributeMaxDynamicSharedMemorySize, SMEM_BYTES);

    __half *ah, *bh;
    cudaGetSymbolAddress((void**)&ah, g_ah);
    cudaGetSymbolAddress((void**)&bh, g_bh);

    // ONE side stream (proven legal, mem delta 0) runs the small prep
    // concurrently with the big A-conversion; GEMM runs alone, unsplit.
    cudaStream_t s1;
    cudaStreamCreateWithFlags(&s1, cudaStreamNonBlocking);
    cudaEvent_t evF, evPrep;
    cudaEventCreateWithFlags(&evF, cudaEventDisableTiming);
    cudaEventCreateWithFlags(&evPrep, cudaEventDisableTiming);

    // fork s1 from origin
    cudaEventRecord(evF, 0);
    cudaStreamWaitEvent(s1, evF, 0);

    // s1: prep (ctx-zero + B-conversion + dec_proj), hidden under cvtA
    init_kernel<<<(B_ * E_ + 255) / 256, 256, 0, s1>>>(out);
    cvt_h_kernel<<<(size_t)D_ * K_ / 4096, 256, 0, s1>>>(We, bh);
    dec_proj_kernel<<<(B_ * (D_ / 4) * 32 + 255) / 256, 256, 0, s1>>>(hidden, Wd);
    cudaEventRecord(evPrep, s1);

    // origin: full A-conversion, join prep, then the GEMM alone
    cvt_h_kernel<<<(size_t)M_ * K_ / 4096, 256>>>(enc, ah);
    cudaStreamWaitEvent(0, evPrep, 0);
    score_mma_kernel<<<dim3(NT, MT), 256, SMEM_BYTES>>>(v);

    softmax_kernel<<<B_, 256>>>(wout);
    context_kernel<<<dim3(E_ / 512, B_, CSPLIT), 256>>>(wout, out);
}

// round 15
// speedup vs baseline: 1.0226x; 1.0226x over previous
#include <cuda_runtime.h>
#include <cuda_fp16.h>
#include <math.h>
#include <stdint.h>

#define B_ 32
#define S_ 2048
#define E_ 1024
#define D_ 1024
#define K_ 1024
#define M_ (S_ * B_)   // 65536

// GEMM tiling
#define CTAM 128
#define CTAN 128
#define CKS 64                 // K per chunk
#define NCHUNK (K_ / CKS)      // 16
#define NT (D_ / CTAN)         // 8
#define MT (M_ / CTAM)         // 512

// SMEM per stage: 2 tiles of 128 rows x 128B = 16KB each
#define OFF_AH 0
#define OFF_BH 16384
#define STAGE_BYTES 32768
#define NSTAGE 3
#define SMEM_BYTES (NSTAGE * STAGE_BYTES)   // 96KB dynamic

__device__ float g_scores[B_ * S_];
__device__ float g_dec[B_ * D_];
__device__ __half g_ah[(size_t)M_ * K_];   // fp16(A)
__device__ __half g_bh[(size_t)D_ * K_];   // fp16(B)

// ---------------------------------------------------------------------------
__device__ __forceinline__ uint32_t smem_u32(const void* p) {
    uint32_t a;
    asm("{ .reg .u64 t; cvta.to.shared.u64 t, %1; cvt.u32.u64 %0, t; }" : "=r"(a) : "l"(p));
    return a;
}

// swizzled offset within a 128-row x 128B tile (8 16B-groups/row, 8-way XOR)
__device__ __forceinline__ uint32_t sw128(uint32_t row, uint32_t g) {
    return (row << 7) | (((g ^ row) & 7u) << 4);
}

__device__ __forceinline__ void ldsm4(uint32_t* r, uint32_t addr) {
    asm volatile("ldmatrix.sync.aligned.m8n8.x4.shared.b16 {%0,%1,%2,%3}, [%4];"
                 : "=r"(r[0]), "=r"(r[1]), "=r"(r[2]), "=r"(r[3]) : "r"(addr));
}

__device__ __forceinline__ void mma_f16(float* d, const uint32_t* a, const uint32_t* b) {
    asm volatile(
        "mma.sync.aligned.m16n8k16.row.col.f32.f16.f16.f32 "
        "{%0,%1,%2,%3}, {%4,%5,%6,%7}, {%8,%9}, {%0,%1,%2,%3};"
        : "+f"(d[0]), "+f"(d[1]), "+f"(d[2]), "+f"(d[3])
        : "r"(a[0]), "r"(a[1]), "r"(a[2]), "r"(a[3]), "r"(b[0]), "r"(b[1]));
}

#define CPA16(dst, src) \
    asm volatile("cp.async.cg.shared.global [%0], [%1], 16;" :: "r"(dst), "l"(src))

// tanh via rational approx (FMA-only, no MUFU in the hot path)
__device__ __forceinline__ float fast_tanh(float x) {
    float cx = fminf(fmaxf(x, -7.90531110763549805f), 7.90531110763549805f);
    float x2 = cx * cx;
    float p = fmaf(x2, -2.76076847742355e-16f, 2.00018790482477e-13f);
    p = fmaf(p, x2, -8.60467152213735e-11f);
    p = fmaf(p, x2, 5.12229709037114e-08f);
    p = fmaf(p, x2, 1.48572235717979e-05f);
    p = fmaf(p, x2, 6.37261928875436e-04f);
    p = fmaf(p, x2, 4.89352455891786e-03f);
    p = p * cx;
    float q = fmaf(x2, 1.19825839466702e-06f, 1.18534705686654e-04f);
    q = fmaf(q, x2, 2.26843463243900e-03f);
    q = fmaf(q, x2, 4.89352518554385e-03f);
    float r = __uint_as_float(0x7EF127EAu - __float_as_uint(q));
    r = r * (2.0f - q * r);
    r = r * (2.0f - q * r);
    r = r * (2.0f - q * r);
    return p * r;
}

// ---------------------------------------------------------------------------
// 0. init: zero scores scratch and the context region of d_out
// ---------------------------------------------------------------------------
__global__ void init_kernel(float* __restrict__ out) {
    int i = blockIdx.x * blockDim.x + threadIdx.x;
    if (i < B_ * S_) g_scores[i] = 0.f;
    if (i < B_ * E_) out[i] = 0.f;
}

// ---------------------------------------------------------------------------
// 1. convert fp32 -> fp16 (16 elems/thread)
// ---------------------------------------------------------------------------
__global__ __launch_bounds__(256)
void cvt_h_kernel(const float* __restrict__ src, __half* __restrict__ dst) {
    size_t idx = ((size_t)blockIdx.x * 256 + threadIdx.x) * 16;
    const float4* s4 = (const float4*)(src + idx);
    float4 f0 = s4[0], f1 = s4[1], f2 = s4[2], f3 = s4[3];
    __half2 h[8];
    h[0] = __floats2half2_rn(f0.x, f0.y);
    h[1] = __floats2half2_rn(f0.z, f0.w);
    h[2] = __floats2half2_rn(f1.x, f1.y);
    h[3] = __floats2half2_rn(f1.z, f1.w);
    h[4] = __floats2half2_rn(f2.x, f2.y);
    h[5] = __floats2half2_rn(f2.z, f2.w);
    h[6] = __floats2half2_rn(f3.x, f3.y);
    h[7] = __floats2half2_rn(f3.z, f3.w);
    *(uint4*)(dst + idx) = *(uint4*)h;
    *(uint4*)(dst + idx + 8) = *(uint4*)(h + 4);
}

// ---------------------------------------------------------------------------
// 2. dec_proj: warp computes 4 outputs (d..d+3) for one b, hidden in regs
// ---------------------------------------------------------------------------
__global__ __launch_bounds__(256)
void dec_proj_kernel(const float* __restrict__ hidden, const float* __restrict__ Wd) {
    int warp = (blockIdx.x * blockDim.x + threadIdx.x) >> 5;
    int lane = threadIdx.x & 31;
    if (warp >= B_ * (D_ / 4)) return;
    int b = warp >> 8;               // / (D_/4)
    int dg = (warp & 255) << 2;
    const float4* h4 = (const float4*)(hidden + (size_t)b * D_);
    float4 ha[8];
#pragma unroll
    for (int i = 0; i < 8; i++) ha[i] = h4[lane + 32 * i];
    float s[4];
#pragma unroll
    for (int j = 0; j < 4; j++) {
        const float4* w4 = (const float4*)(Wd + (size_t)(dg + j) * D_);
        float acc = 0.f;
#pragma unroll
        for (int i = 0; i < 8; i++) {
            float4 w = w4[lane + 32 * i];
            acc += ha[i].x * w.x + ha[i].y * w.y + ha[i].z * w.z + ha[i].w * w.w;
        }
        s[j] = acc;
    }
#pragma unroll
    for (int j = 0; j < 4; j++)
#pragma unroll
        for (int o = 16; o; o >>= 1) s[j] += __shfl_down_sync(0xffffffffu, s[j], o);
    if (lane == 0)
        *(float4*)(g_dec + (size_t)b * D_ + dg) = make_float4(s[0], s[1], s[2], s[3]);
}

// ---------------------------------------------------------------------------
// 3. Fused scores GEMM: fp16, 3-stage cp.async ring, single unsplit launch;
//    epilogue combines wn-halves in SMEM -> one atomicAdd per row per CTA
// ---------------------------------------------------------------------------
__global__ __launch_bounds__(256, 2)
void score_mma_kernel(const float* __restrict__ v) {
    extern __shared__ __align__(1024) char smem[];
    const uint32_t sb = smem_u32(smem);

    const int tid = threadIdx.x;
    const int wid = tid >> 5;
    const int lane = tid & 31;
    const int wm = wid >> 1;          // 0..3
    const int wn = wid & 1;           // 0..1
    const int n_base = blockIdx.x * CTAN;
    const size_t m_base = (size_t)blockIdx.y * CTAM;

    // per-thread copy task: row lr (0..127), half lh -> 4 16B groups per tile
    const int lr = tid >> 1;
    const int lh = tid & 1;
    const __half* Ah_r = g_ah + (m_base + lr) * (size_t)K_;
    const __half* Bh_r = g_bh + (size_t)(n_base + lr) * K_;
    uint32_t so[4];
#pragma unroll
    for (int i = 0; i < 4; i++) so[i] = sw128(lr, lh * 4 + i);

#define PREFETCH(c, st)                                                       \
    {                                                                         \
        uint32_t stb_ = sb + (st) * STAGE_BYTES;                              \
        int ko_ = (c) * CKS;                                                  \
        _Pragma("unroll")                                                     \
        for (int i_ = 0; i_ < 4; i_++) {                                      \
            int ge_ = ko_ + (lh * 4 + i_) * 8;                                \
            CPA16(stb_ + OFF_AH + so[i_], Ah_r + ge_);                        \
            CPA16(stb_ + OFF_BH + so[i_], Bh_r + ge_);                        \
        }                                                                     \
    }

    float acc[2][8][4];
#pragma unroll
    for (int mt = 0; mt < 2; mt++)
#pragma unroll
        for (int j = 0; j < 8; j++)
#pragma unroll
            for (int cc = 0; cc < 4; cc++) acc[mt][j][cc] = 0.f;

    // ldmatrix per-lane address components
    const uint32_t a_row = wm * 32 + (lane & 15);
    const uint32_t a_kg = (uint32_t)(lane >> 4);
    const uint32_t b_row_lo = wn * 64 + (lane & 7) + ((lane & 16) ? 8 : 0);
    const uint32_t b_kg = (uint32_t)((lane >> 3) & 1);

    PREFETCH(0, 0);
    asm volatile("cp.async.commit_group;" ::: "memory");
    PREFETCH(1, 1);
    asm volatile("cp.async.commit_group;" ::: "memory");

    int st = 0, stp = 2;
    for (int c = 0; c < NCHUNK; c++) {
        asm volatile("cp.async.wait_group 1;" ::: "memory");
        __syncthreads();   // stage st ready; all warps done reading stage stp

        // early prefetch for chunk c+2 into the just-freed stage stp
        if (c + 2 < NCHUNK) PREFETCH(c + 2, stp);
        asm volatile("cp.async.commit_group;" ::: "memory");

        const uint32_t stb = sb + st * STAGE_BYTES;
#pragma unroll
        for (int ks = 0; ks < 4; ks++) {
            uint32_t ah[2][4];
#pragma unroll
            for (int mt = 0; mt < 2; mt++) {
                uint32_t off = sw128(a_row + mt * 16, 2 * ks + a_kg);
                ldsm4(ah[mt], stb + OFF_AH + off);
            }
#pragma unroll
            for (int half = 0; half < 2; half++) {
                uint32_t bh[4][2];
#pragma unroll
                for (int j2 = 0; j2 < 2; j2++) {
                    uint32_t off = sw128(b_row_lo + (half * 2 + j2) * 16, 2 * ks + b_kg);
                    uint32_t t[4];
                    ldsm4(t, stb + OFF_BH + off);
                    bh[j2 * 2][0] = t[0]; bh[j2 * 2][1] = t[1];
                    bh[j2 * 2 + 1][0] = t[2]; bh[j2 * 2 + 1][1] = t[3];
                }
#pragma unroll
                for (int mt = 0; mt < 2; mt++)
#pragma unroll
                    for (int j = 0; j < 4; j++)
                        mma_f16(acc[mt][half * 4 + j], ah[mt], bh[j]);
            }
        }
        st = (st == 2) ? 0 : st + 1;
        stp = (stp == 2) ? 0 : stp + 1;
    }
    asm volatile("cp.async.wait_group 0;" ::: "memory");
    __syncthreads();

    // ---- epilogue: stage dec tile + v into smem, tanh + v-dot, reduce ----
    float* sdec = (float*)smem;             // [32][128] = 16KB
    float* sv = (float*)(smem + 16384);     // [128]   (512 B)
    float* sred = (float*)(smem + 17408);   // [128][2] (1 KB) row x wn partials
    for (int i = tid; i < B_ * CTAN; i += 256) {
        int b = i >> 7, n = i & (CTAN - 1);
        sdec[b * CTAN + n] = g_dec[b * D_ + n_base + n];
    }
    if (tid < CTAN) sv[tid] = v[n_base + tid];
    __syncthreads();

#pragma unroll
    for (int mt = 0; mt < 2; mt++) {
        int rowA = wm * 32 + mt * 16 + (lane >> 2);
        int b0 = rowA & 31, b1 = (rowA + 8) & 31;
        float s0 = 0.f, s1 = 0.f;
#pragma unroll
        for (int j = 0; j < 8; j++) {
            int nc = wn * 64 + j * 8 + (lane & 3) * 2;
            float v0 = sv[nc], v1 = sv[nc + 1];
            s0 = fmaf(fast_tanh(acc[mt][j][0] + sdec[b0 * CTAN + nc]), v0, s0);
            s0 = fmaf(fast_tanh(acc[mt][j][1] + sdec[b0 * CTAN + nc + 1]), v1, s0);
            s1 = fmaf(fast_tanh(acc[mt][j][2] + sdec[b1 * CTAN + nc]), v0, s1);
            s1 = fmaf(fast_tanh(acc[mt][j][3] + sdec[b1 * CTAN + nc + 1]), v1, s1);
        }
        s0 += __shfl_xor_sync(0xffffffffu, s0, 1);
        s0 += __shfl_xor_sync(0xffffffffu, s0, 2);
        s1 += __shfl_xor_sync(0xffffffffu, s1, 1);
        s1 += __shfl_xor_sync(0xffffffffu, s1, 2);
        if ((lane & 3) == 0) {
            // each (row, wn) pair written exactly once across the CTA
            sred[rowA * 2 + wn] = s0;
            sred[(rowA + 8) * 2 + wn] = s1;
        }
    }
    __syncthreads();
    // fold the two wn halves; one atomic per row per CTA (8/element chip-wide)
    if (tid < CTAM) {
        size_t m = m_base + tid;
        atomicAdd(&g_scores[(m & 31) * S_ + (m >> 5)],
                  sred[tid * 2] + sred[tid * 2 + 1]);
    }
}

// ---------------------------------------------------------------------------
// 4. softmax over S per batch
// ---------------------------------------------------------------------------
__global__ __launch_bounds__(256)
void softmax_kernel(float* __restrict__ wout) {
    int b = blockIdx.x;
    int tid = threadIdx.x;
    __shared__ float sm[256];

    float vals[8];
    float mx = -1e30f;
#pragma unroll
    for (int i = 0; i < 8; i++) {
        vals[i] = g_scores[b * S_ + tid + i * 256];
        mx = fmaxf(mx, vals[i]);
    }
    sm[tid] = mx; __syncthreads();
    for (int o = 128; o; o >>= 1) {
        if (tid < o) sm[tid] = fmaxf(sm[tid], sm[tid + o]);
        __syncthreads();
    }
    mx = sm[0]; __syncthreads();

    float sum = 0.f;
#pragma unroll
    for (int i = 0; i < 8; i++) { vals[i] = expf(vals[i] - mx); sum += vals[i]; }
    sm[tid] = sum; __syncthreads();
    for (int o = 128; o; o >>= 1) {
        if (tid < o) sm[tid] += sm[tid + o];
        __syncthreads();
    }
    float inv = 1.f / sm[0];
#pragma unroll
    for (int i = 0; i < 8; i++) wout[b * S_ + tid + i * 256] = vals[i] * inv;
}

// ---------------------------------------------------------------------------
// 5. context[b,e] = sum_s w[b,s] * enc_fp16[s,b,e]  (reads g_ah, half2)
// ---------------------------------------------------------------------------
#define CSPLIT 8
__global__ __launch_bounds__(256)
void context_kernel(const float* __restrict__ w, float* __restrict__ ctx) {
    int e2 = blockIdx.x * 256 + threadIdx.x;   // half2 index, 0..511
    int b = blockIdx.y;
    int s0 = blockIdx.z * (S_ / CSPLIT);
    const __half2* base = (const __half2*)g_ah + (size_t)b * (K_ / 2) + e2;
    const size_t str = (size_t)B_ * (K_ / 2);
    float ax0 = 0.f, ay0 = 0.f, ax1 = 0.f, ay1 = 0.f;
    float ax2 = 0.f, ay2 = 0.f, ax3 = 0.f, ay3 = 0.f;
#pragma unroll 2
    for (int s = s0; s < s0 + S_ / CSPLIT; s += 4) {
        float w0 = w[b * S_ + s + 0], w1 = w[b * S_ + s + 1];
        float w2 = w[b * S_ + s + 2], w3 = w[b * S_ + s + 3];
        float2 f0 = __half22float2(base[(size_t)(s + 0) * str]);
        float2 f1 = __half22float2(base[(size_t)(s + 1) * str]);
        float2 f2 = __half22float2(base[(size_t)(s + 2) * str]);
        float2 f3 = __half22float2(base[(size_t)(s + 3) * str]);
        ax0 = fmaf(w0, f0.x, ax0); ay0 = fmaf(w0, f0.y, ay0);
        ax1 = fmaf(w1, f1.x, ax1); ay1 = fmaf(w1, f1.y, ay1);
        ax2 = fmaf(w2, f2.x, ax2); ay2 = fmaf(w2, f2.y, ay2);
        ax3 = fmaf(w3, f3.x, ax3); ay3 = fmaf(w3, f3.y, ay3);
    }
    atomicAdd(&ctx[b * E_ + 2 * e2], (ax0 + ax1) + (ax2 + ax3));
    atomicAdd(&ctx[b * E_ + 2 * e2 + 1], (ay0 + ay1) + (ay2 + ay3));
}

// ---------------------------------------------------------------------------
extern "C" void kernel_launch(void* const* d_in, const int* in_sizes, int n_in,
                              void* d_out, int out_size) {
    const float* hidden = (const float*)d_in[0];  // [B,D]
    const float* enc    = (const float*)d_in[1];  // [S,B,E]
    const float* We     = (const float*)d_in[2];  // [D,E]
    const float* Wd     = (const float*)d_in[3];  // [D,D]
    const float* v      = (const float*)d_in[4];  // [D]
    float* out = (float*)d_out;                   // [B*E context | B*S weights]
    float* wout = out + B_ * E_;

    cudaFuncSetAttribute(score_mma_kernel,
                         cudaFuncAttributeMaxDynamicSharedMemorySize, SMEM_BYTES);

    __half *ah, *bh;
    cudaGetSymbolAddress((void**)&ah, g_ah);
    cudaGetSymbolAddress((void**)&bh, g_bh);

    // ONE side stream (proven legal, mem delta 0) runs the small prep
    // concurrently with the big A-conversion; GEMM runs alone, unsplit.
    cudaStream_t s1;
    cudaStreamCreateWithFlags(&s1, cudaStreamNonBlocking);
    cudaEvent_t evF, evPrep;
    cudaEventCreateWithFlags(&evF, cudaEventDisableTiming);
    cudaEventCreateWithFlags(&evPrep, cudaEventDisableTiming);

    // fork s1 from origin
    cudaEventRecord(evF, 0);
    cudaStreamWaitEvent(s1, evF, 0);

    // s1: prep (init + B-conversion + dec_proj), hidden under cvtA
    init_kernel<<<(B_ * S_ + 255) / 256, 256, 0, s1>>>(out);
    cvt_h_kernel<<<(size_t)D_ * K_ / 4096, 256, 0, s1>>>(We, bh);
    dec_proj_kernel<<<(B_ * (D_ / 4) * 32 + 255) / 256, 256, 0, s1>>>(hidden, Wd);
    cudaEventRecord(evPrep, s1);

    // origin: full A-conversion, join prep, then the GEMM alone
    cvt_h_kernel<<<(size_t)M_ * K_ / 4096, 256>>>(enc, ah);
    cudaStreamWaitEvent(0, evPrep, 0);
    score_mma_kernel<<<dim3(NT, MT), 256, SMEM_BYTES>>>(v);

    softmax_kernel<<<B_, 256>>>(wout);
    context_kernel<<<dim3(E_ / 512, B_, CSPLIT), 256>>>(wout, out);
}

// round 16
// speedup vs baseline: 1.0315x; 1.0087x over previous
#include <cuda_runtime.h>
#include <cuda_fp16.h>
#include <math.h>
#include <stdint.h>

#define B_ 32
#define S_ 2048
#define E_ 1024
#define D_ 1024
#define K_ 1024
#define M_ (S_ * B_)   // 65536

// GEMM tiling
#define CTAM 128
#define CTAN 128
#define CKS 64                 // K per chunk
#define NCHUNK (K_ / CKS)      // 16
#define NT (D_ / CTAN)         // 8
#define MT (M_ / CTAM)         // 512

// SMEM per stage: 2 tiles of 128 rows x 128B = 16KB each
#define OFF_AH 0
#define OFF_BH 16384
#define STAGE_BYTES 32768
#define NSTAGE 3
#define SMEM_BYTES (NSTAGE * STAGE_BYTES)   // 96KB dynamic

__device__ float g_scores[B_ * S_];
__device__ float g_dec[B_ * D_];
__device__ __half g_ah[(size_t)M_ * K_];   // fp16(A)
__device__ __half g_bh[(size_t)D_ * K_];   // fp16(B)

// ---------------------------------------------------------------------------
__device__ __forceinline__ uint32_t smem_u32(const void* p) {
    uint32_t a;
    asm("{ .reg .u64 t; cvta.to.shared.u64 t, %1; cvt.u32.u64 %0, t; }" : "=r"(a) : "l"(p));
    return a;
}

// swizzled offset within a 128-row x 128B tile (8 16B-groups/row, 8-way XOR)
__device__ __forceinline__ uint32_t sw128(uint32_t row, uint32_t g) {
    return (row << 7) | (((g ^ row) & 7u) << 4);
}

__device__ __forceinline__ void ldsm4(uint32_t* r, uint32_t addr) {
    asm volatile("ldmatrix.sync.aligned.m8n8.x4.shared.b16 {%0,%1,%2,%3}, [%4];"
                 : "=r"(r[0]), "=r"(r[1]), "=r"(r[2]), "=r"(r[3]) : "r"(addr));
}

__device__ __forceinline__ void mma_f16(float* d, const uint32_t* a, const uint32_t* b) {
    asm volatile(
        "mma.sync.aligned.m16n8k16.row.col.f32.f16.f16.f32 "
        "{%0,%1,%2,%3}, {%4,%5,%6,%7}, {%8,%9}, {%0,%1,%2,%3};"
        : "+f"(d[0]), "+f"(d[1]), "+f"(d[2]), "+f"(d[3])
        : "r"(a[0]), "r"(a[1]), "r"(a[2]), "r"(a[3]), "r"(b[0]), "r"(b[1]));
}

#define CPA16(dst, src) \
    asm volatile("cp.async.cg.shared.global [%0], [%1], 16;" :: "r"(dst), "l"(src))

// tanh via rational approx (FMA-only, no MUFU in the hot path)
__device__ __forceinline__ float fast_tanh(float x) {
    float cx = fminf(fmaxf(x, -7.90531110763549805f), 7.90531110763549805f);
    float x2 = cx * cx;
    float p = fmaf(x2, -2.76076847742355e-16f, 2.00018790482477e-13f);
    p = fmaf(p, x2, -8.60467152213735e-11f);
    p = fmaf(p, x2, 5.12229709037114e-08f);
    p = fmaf(p, x2, 1.48572235717979e-05f);
    p = fmaf(p, x2, 6.37261928875436e-04f);
    p = fmaf(p, x2, 4.89352455891786e-03f);
    p = p * cx;
    float q = fmaf(x2, 1.19825839466702e-06f, 1.18534705686654e-04f);
    q = fmaf(q, x2, 2.26843463243900e-03f);
    q = fmaf(q, x2, 4.89352518554385e-03f);
    float r = __uint_as_float(0x7EF127EAu - __float_as_uint(q));
    r = r * (2.0f - q * r);
    r = r * (2.0f - q * r);
    r = r * (2.0f - q * r);
    return p * r;
}

// ---------------------------------------------------------------------------
// 0. init: zero scores scratch and the context region of d_out
// ---------------------------------------------------------------------------
__global__ void init_kernel(float* __restrict__ out) {
    int i = blockIdx.x * blockDim.x + threadIdx.x;
    if (i < B_ * S_) g_scores[i] = 0.f;
    if (i < B_ * E_) out[i] = 0.f;
}

// ---------------------------------------------------------------------------
// 1. convert fp32 -> fp16 (16 elems/thread)
// ---------------------------------------------------------------------------
__global__ __launch_bounds__(256)
void cvt_h_kernel(const float* __restrict__ src, __half* __restrict__ dst) {
    size_t idx = ((size_t)blockIdx.x * 256 + threadIdx.x) * 16;
    const float4* s4 = (const float4*)(src + idx);
    float4 f0 = s4[0], f1 = s4[1], f2 = s4[2], f3 = s4[3];
    __half2 h[8];
    h[0] = __floats2half2_rn(f0.x, f0.y);
    h[1] = __floats2half2_rn(f0.z, f0.w);
    h[2] = __floats2half2_rn(f1.x, f1.y);
    h[3] = __floats2half2_rn(f1.z, f1.w);
    h[4] = __floats2half2_rn(f2.x, f2.y);
    h[5] = __floats2half2_rn(f2.z, f2.w);
    h[6] = __floats2half2_rn(f3.x, f3.y);
    h[7] = __floats2half2_rn(f3.z, f3.w);
    *(uint4*)(dst + idx) = *(uint4*)h;
    *(uint4*)(dst + idx + 8) = *(uint4*)(h + 4);
}

// ---------------------------------------------------------------------------
// 2. dec_proj: warp computes 4 outputs (d..d+3) for one b, hidden in regs
// ---------------------------------------------------------------------------
__global__ __launch_bounds__(256)
void dec_proj_kernel(const float* __restrict__ hidden, const float* __restrict__ Wd) {
    int warp = (blockIdx.x * blockDim.x + threadIdx.x) >> 5;
    int lane = threadIdx.x & 31;
    if (warp >= B_ * (D_ / 4)) return;
    int b = warp >> 8;               // / (D_/4)
    int dg = (warp & 255) << 2;
    const float4* h4 = (const float4*)(hidden + (size_t)b * D_);
    float4 ha[8];
#pragma unroll
    for (int i = 0; i < 8; i++) ha[i] = h4[lane + 32 * i];
    float s[4];
#pragma unroll
    for (int j = 0; j < 4; j++) {
        const float4* w4 = (const float4*)(Wd + (size_t)(dg + j) * D_);
        float acc = 0.f;
#pragma unroll
        for (int i = 0; i < 8; i++) {
            float4 w = w4[lane + 32 * i];
            acc += ha[i].x * w.x + ha[i].y * w.y + ha[i].z * w.z + ha[i].w * w.w;
        }
        s[j] = acc;
    }
#pragma unroll
    for (int j = 0; j < 4; j++)
#pragma unroll
        for (int o = 16; o; o >>= 1) s[j] += __shfl_down_sync(0xffffffffu, s[j], o);
    if (lane == 0)
        *(float4*)(g_dec + (size_t)b * D_ + dg) = make_float4(s[0], s[1], s[2], s[3]);
}

// ---------------------------------------------------------------------------
// 3. Fused scores GEMM: fp16, 3-stage cp.async ring, single unsplit launch;
//    epilogue combines wn-halves in SMEM -> one atomicAdd per row per CTA
// ---------------------------------------------------------------------------
__global__ __launch_bounds__(256, 2)
void score_mma_kernel(const float* __restrict__ v) {
    extern __shared__ __align__(1024) char smem[];
    const uint32_t sb = smem_u32(smem);

    const int tid = threadIdx.x;
    const int wid = tid >> 5;
    const int lane = tid & 31;
    const int wm = wid >> 1;          // 0..3
    const int wn = wid & 1;           // 0..1
    const int n_base = blockIdx.x * CTAN;
    const size_t m_base = (size_t)blockIdx.y * CTAM;

    // per-thread copy task: row lr (0..127), half lh -> 4 16B groups per tile
    const int lr = tid >> 1;
    const int lh = tid & 1;
    const __half* Ah_r = g_ah + (m_base + lr) * (size_t)K_;
    const __half* Bh_r = g_bh + (size_t)(n_base + lr) * K_;
    uint32_t so[4];
#pragma unroll
    for (int i = 0; i < 4; i++) so[i] = sw128(lr, lh * 4 + i);

#define PREFETCH(c, st)                                                       \
    {                                                                         \
        uint32_t stb_ = sb + (st) * STAGE_BYTES;                              \
        int ko_ = (c) * CKS;                                                  \
        _Pragma("unroll")                                                     \
        for (int i_ = 0; i_ < 4; i_++) {                                      \
            int ge_ = ko_ + (lh * 4 + i_) * 8;                                \
            CPA16(stb_ + OFF_AH + so[i_], Ah_r + ge_);                        \
            CPA16(stb_ + OFF_BH + so[i_], Bh_r + ge_);                        \
        }                                                                     \
    }

    float acc[2][8][4];
#pragma unroll
    for (int mt = 0; mt < 2; mt++)
#pragma unroll
        for (int j = 0; j < 8; j++)
#pragma unroll
            for (int cc = 0; cc < 4; cc++) acc[mt][j][cc] = 0.f;

    // ldmatrix per-lane address components
    const uint32_t a_row = wm * 32 + (lane & 15);
    const uint32_t a_kg = (uint32_t)(lane >> 4);
    const uint32_t b_row_lo = wn * 64 + (lane & 7) + ((lane & 16) ? 8 : 0);
    const uint32_t b_kg = (uint32_t)((lane >> 3) & 1);

    PREFETCH(0, 0);
    asm volatile("cp.async.commit_group;" ::: "memory");
    PREFETCH(1, 1);
    asm volatile("cp.async.commit_group;" ::: "memory");

    int st = 0, stp = 2;
    for (int c = 0; c < NCHUNK; c++) {
        asm volatile("cp.async.wait_group 1;" ::: "memory");
        __syncthreads();   // stage st ready; all warps done reading stage stp

        // early prefetch for chunk c+2 into the just-freed stage stp
        if (c + 2 < NCHUNK) PREFETCH(c + 2, stp);
        asm volatile("cp.async.commit_group;" ::: "memory");

        const uint32_t stb = sb + st * STAGE_BYTES;
#pragma unroll
        for (int ks = 0; ks < 4; ks++) {
            uint32_t ah[2][4];
#pragma unroll
            for (int mt = 0; mt < 2; mt++) {
                uint32_t off = sw128(a_row + mt * 16, 2 * ks + a_kg);
                ldsm4(ah[mt], stb + OFF_AH + off);
            }
#pragma unroll
            for (int half = 0; half < 2; half++) {
                uint32_t bh[4][2];
#pragma unroll
                for (int j2 = 0; j2 < 2; j2++) {
                    uint32_t off = sw128(b_row_lo + (half * 2 + j2) * 16, 2 * ks + b_kg);
                    uint32_t t[4];
                    ldsm4(t, stb + OFF_BH + off);
                    bh[j2 * 2][0] = t[0]; bh[j2 * 2][1] = t[1];
                    bh[j2 * 2 + 1][0] = t[2]; bh[j2 * 2 + 1][1] = t[3];
                }
#pragma unroll
                for (int mt = 0; mt < 2; mt++)
#pragma unroll
                    for (int j = 0; j < 4; j++)
                        mma_f16(acc[mt][half * 4 + j], ah[mt], bh[j]);
            }
        }
        st = (st == 2) ? 0 : st + 1;
        stp = (stp == 2) ? 0 : stp + 1;
    }
    asm volatile("cp.async.wait_group 0;" ::: "memory");
    __syncthreads();

    // ---- epilogue: stage dec tile + v into smem, tanh + v-dot, reduce ----
    float* sdec = (float*)smem;             // [32][128] = 16KB
    float* sv = (float*)(smem + 16384);     // [128]   (512 B)
    float* sred = (float*)(smem + 17408);   // [128][2] (1 KB) row x wn partials
    for (int i = tid; i < B_ * CTAN; i += 256) {
        int b = i >> 7, n = i & (CTAN - 1);
        sdec[b * CTAN + n] = g_dec[b * D_ + n_base + n];
    }
    if (tid < CTAN) sv[tid] = v[n_base + tid];
    __syncthreads();

#pragma unroll
    for (int mt = 0; mt < 2; mt++) {
        int rowA = wm * 32 + mt * 16 + (lane >> 2);
        int b0 = rowA & 31, b1 = (rowA + 8) & 31;
        float s0 = 0.f, s1 = 0.f;
#pragma unroll
        for (int j = 0; j < 8; j++) {
            int nc = wn * 64 + j * 8 + (lane & 3) * 2;
            float v0 = sv[nc], v1 = sv[nc + 1];
            s0 = fmaf(fast_tanh(acc[mt][j][0] + sdec[b0 * CTAN + nc]), v0, s0);
            s0 = fmaf(fast_tanh(acc[mt][j][1] + sdec[b0 * CTAN + nc + 1]), v1, s0);
            s1 = fmaf(fast_tanh(acc[mt][j][2] + sdec[b1 * CTAN + nc]), v0, s1);
            s1 = fmaf(fast_tanh(acc[mt][j][3] + sdec[b1 * CTAN + nc + 1]), v1, s1);
        }
        s0 += __shfl_xor_sync(0xffffffffu, s0, 1);
        s0 += __shfl_xor_sync(0xffffffffu, s0, 2);
        s1 += __shfl_xor_sync(0xffffffffu, s1, 1);
        s1 += __shfl_xor_sync(0xffffffffu, s1, 2);
        if ((lane & 3) == 0) {
            sred[rowA * 2 + wn] = s0;
            sred[(rowA + 8) * 2 + wn] = s1;
        }
    }
    __syncthreads();
    // fold the two wn halves; one atomic per row per CTA (8/element chip-wide)
    if (tid < CTAM) {
        size_t m = m_base + tid;
        atomicAdd(&g_scores[(m & 31) * S_ + (m >> 5)],
                  sred[tid * 2] + sred[tid * 2 + 1]);
    }
}

// ---------------------------------------------------------------------------
// 4. softmax over S per batch
// ---------------------------------------------------------------------------
__global__ __launch_bounds__(256)
void softmax_kernel(float* __restrict__ wout) {
    int b = blockIdx.x;
    int tid = threadIdx.x;
    __shared__ float sm[256];

    float vals[8];
    float mx = -1e30f;
#pragma unroll
    for (int i = 0; i < 8; i++) {
        vals[i] = g_scores[b * S_ + tid + i * 256];
        mx = fmaxf(mx, vals[i]);
    }
    sm[tid] = mx; __syncthreads();
    for (int o = 128; o; o >>= 1) {
        if (tid < o) sm[tid] = fmaxf(sm[tid], sm[tid + o]);
        __syncthreads();
    }
    mx = sm[0]; __syncthreads();

    float sum = 0.f;
#pragma unroll
    for (int i = 0; i < 8; i++) { vals[i] = expf(vals[i] - mx); sum += vals[i]; }
    sm[tid] = sum; __syncthreads();
    for (int o = 128; o; o >>= 1) {
        if (tid < o) sm[tid] += sm[tid + o];
        __syncthreads();
    }
    float inv = 1.f / sm[0];
#pragma unroll
    for (int i = 0; i < 8; i++) wout[b * S_ + tid + i * 256] = vals[i] * inv;
}

// ---------------------------------------------------------------------------
// 5. context[b,e] = sum_s w[b,s] * enc_fp16[s,b,e]
//    16B loads: each thread handles 8 consecutive elements per s-step
// ---------------------------------------------------------------------------
#define CSPLIT 16
__global__ __launch_bounds__(128)
void context_kernel(const float* __restrict__ w, float* __restrict__ ctx) {
    int e8 = threadIdx.x;                     // 0..127, covers 8 elems each
    int b = blockIdx.y;
    int s0 = blockIdx.z * (S_ / CSPLIT);      // 128 s-steps per CTA
    const uint4* base = (const uint4*)(g_ah + (size_t)b * K_) + e8;
    const size_t str = (size_t)B_ * K_ / 8;   // row stride in uint4 units
    const float* wrow = w + b * S_;

    float acc[8];
#pragma unroll
    for (int j = 0; j < 8; j++) acc[j] = 0.f;

#pragma unroll 2
    for (int s = s0; s < s0 + S_ / CSPLIT; s += 2) {
        float w0 = wrow[s], w1 = wrow[s + 1];
        uint4 r0 = base[(size_t)s * str];
        uint4 r1 = base[(size_t)(s + 1) * str];
        const __half2* h0 = (const __half2*)&r0;
        const __half2* h1 = (const __half2*)&r1;
#pragma unroll
        for (int j = 0; j < 4; j++) {
            float2 f0 = __half22float2(h0[j]);
            float2 f1 = __half22float2(h1[j]);
            acc[2 * j] = fmaf(w0, f0.x, acc[2 * j]);
            acc[2 * j + 1] = fmaf(w0, f0.y, acc[2 * j + 1]);
            acc[2 * j] = fmaf(w1, f1.x, acc[2 * j]);
            acc[2 * j + 1] = fmaf(w1, f1.y, acc[2 * j + 1]);
        }
    }
    float* dst = ctx + b * E_ + e8 * 8;
#pragma unroll
    for (int j = 0; j < 8; j++) atomicAdd(dst + j, acc[j]);
}

// ---------------------------------------------------------------------------
extern "C" void kernel_launch(void* const* d_in, const int* in_sizes, int n_in,
                              void* d_out, int out_size) {
    const float* hidden = (const float*)d_in[0];  // [B,D]
    const float* enc    = (const float*)d_in[1];  // [S,B,E]
    const float* We     = (const float*)d_in[2];  // [D,E]
    const float* Wd     = (const float*)d_in[3];  // [D,D]
    const float* v      = (const float*)d_in[4];  // [D]
    float* out = (float*)d_out;                   // [B*E context | B*S weights]
    float* wout = out + B_ * E_;

    cudaFuncSetAttribute(score_mma_kernel,
                         cudaFuncAttributeMaxDynamicSharedMemorySize, SMEM_BYTES);

    __half *ah, *bh;
    cudaGetSymbolAddress((void**)&ah, g_ah);
    cudaGetSymbolAddress((void**)&bh, g_bh);

    // ONE side stream (proven legal, mem delta 0) runs the small prep
    // concurrently with the big A-conversion; GEMM runs alone, unsplit.
    cudaStream_t s1;
    cudaStreamCreateWithFlags(&s1, cudaStreamNonBlocking);
    cudaEvent_t evF, evPrep;
    cudaEventCreateWithFlags(&evF, cudaEventDisableTiming);
    cudaEventCreateWithFlags(&evPrep, cudaEventDisableTiming);

    // fork s1 from origin
    cudaEventRecord(evF, 0);
    cudaStreamWaitEvent(s1, evF, 0);

    // s1: prep (init + B-conversion + dec_proj), hidden under cvtA
    init_kernel<<<(B_ * S_ + 255) / 256, 256, 0, s1>>>(out);
    cvt_h_kernel<<<(size_t)D_ * K_ / 4096, 256, 0, s1>>>(We, bh);
    dec_proj_kernel<<<(B_ * (D_ / 4) * 32 + 255) / 256, 256, 0, s1>>>(hidden, Wd);
    cudaEventRecord(evPrep, s1);

    // origin: full A-conversion, join prep, then the GEMM alone
    cvt_h_kernel<<<(size_t)M_ * K_ / 4096, 256>>>(enc, ah);
    cudaStreamWaitEvent(0, evPrep, 0);
    score_mma_kernel<<<dim3(NT, MT), 256, SMEM_BYTES>>>(v);

    softmax_kernel<<<B_, 256>>>(wout);
    context_kernel<<<dim3(1, B_, CSPLIT), 128>>>(wout, out);
}